// round 1
// baseline (speedup 1.0000x reference)
#include <cuda_runtime.h>
#include <math.h>

// Problem constants
#define BD 4
#define ND 2048
#define CD 256
#define INNER 1024
#define ROWS (BD*ND)          // 8192
#define EPS 1e-5f
#define ATT_SCALE 0.125f      // 64^-0.5

// ---------------- scratch (device globals; allocation-free rule) -------------
__device__ float g_qn[ROWS*CD];
__device__ float g_kn[ROWS*CD];
__device__ float g_vn[ROWS*CD];
__device__ float g_qp[ROWS*INNER];
__device__ float g_kp[ROWS*INNER];
__device__ float g_vp[ROWS*INNER];
__device__ float g_attn[(long long)BD*ND*ND];   // 64 MB
__device__ float g_x[ROWS*INNER];

// ---------------- block reductions ----------------
__device__ __forceinline__ float warp_sum(float v) {
    #pragma unroll
    for (int o = 16; o; o >>= 1) v += __shfl_xor_sync(0xffffffffu, v, o);
    return v;
}
__device__ __forceinline__ float warp_max(float v) {
    #pragma unroll
    for (int o = 16; o; o >>= 1) v = fmaxf(v, __shfl_xor_sync(0xffffffffu, v, o));
    return v;
}

__device__ __forceinline__ float block_sum256(float v, float* shm) {
    v = warp_sum(v);
    int w = threadIdx.x >> 5;
    if ((threadIdx.x & 31) == 0) shm[w] = v;
    __syncthreads();
    if (threadIdx.x == 0) {
        float s = 0.f;
        #pragma unroll
        for (int i = 0; i < 8; i++) s += shm[i];
        shm[8] = s;
    }
    __syncthreads();
    float r = shm[8];
    __syncthreads();
    return r;
}
__device__ __forceinline__ float block_max256(float v, float* shm) {
    v = warp_max(v);
    int w = threadIdx.x >> 5;
    if ((threadIdx.x & 31) == 0) shm[w] = v;
    __syncthreads();
    if (threadIdx.x == 0) {
        float m = shm[0];
        #pragma unroll
        for (int i = 1; i < 8; i++) m = fmaxf(m, shm[i]);
        shm[8] = m;
    }
    __syncthreads();
    float r = shm[8];
    __syncthreads();
    return r;
}

// ---------------- LayerNorm: one block (256 thr) per row, 3 tensors ---------
__global__ void ln_kernel(const float* __restrict__ q, const float* __restrict__ k,
                          const float* __restrict__ v, const float* __restrict__ g,
                          const float* __restrict__ b) {
    __shared__ float shm[9];
    const float* src;
    float* dst;
    int which = blockIdx.y;
    long long off = (long long)blockIdx.x * CD;
    if (which == 0)      { src = q + off; dst = g_qn + off; }
    else if (which == 1) { src = k + off; dst = g_kn + off; }
    else                 { src = v + off; dst = g_vn + off; }

    int t = threadIdx.x;            // 256 threads == CD
    float x = src[t];
    float mean = block_sum256(x, shm) * (1.0f / CD);
    float d = x - mean;
    float var = block_sum256(d * d, shm) * (1.0f / CD);
    float inv = rsqrtf(var + EPS);
    dst[t] = d * inv * g[t] + b[t];
}

// ---------------- fp32 SIMT GEMM: C = alpha * A @ B(^T) (+ bias) ------------
// A: [M,K] row-major.  B: !TRANS_B -> [K,N],  TRANS_B -> [N,K].
// Tile 128x128x8, 256 threads, 8x8 micro-tile. All dims divisible by tiles.
template<bool TRANS_B, bool HAS_BIAS>
__global__ __launch_bounds__(256)
void gemm_kernel(const float* __restrict__ A, const float* __restrict__ B,
                 const float* __restrict__ bias, float* __restrict__ Cout,
                 int M, int N, int K, float alpha,
                 long long strideA, long long strideB, long long strideC) {
    constexpr int BM = 128, BN = 128, BK = 8, TM = 8, TN = 8;
    __shared__ float As[BK][BM];
    __shared__ float Bs[BK][BN];

    A    += (long long)blockIdx.z * strideA;
    B    += (long long)blockIdx.z * strideB;
    Cout += (long long)blockIdx.z * strideC;

    const int tid = threadIdx.x;
    const int tx = tid & 15;         // 0..15 -> N
    const int ty = tid >> 4;         // 0..15 -> M

    const int aRow = tid >> 1;             // 0..127
    const int aCol = (tid & 1) * 4;        // 0 or 4

    int bRow, bCol;
    if (!TRANS_B) { bRow = tid >> 5; bCol = (tid & 31) * 4; }  // 8x128 tile
    else          { bRow = tid >> 1; bCol = (tid & 1) * 4; }   // 128x8 tile

    float acc[TM][TN] = {};

    const float* aPtr = A + (long long)(blockIdx.y * BM + aRow) * K;

    for (int k0 = 0; k0 < K; k0 += BK) {
        // A tile (transposed into As[k][m])
        float4 av = *reinterpret_cast<const float4*>(aPtr + k0 + aCol);
        As[aCol + 0][aRow] = av.x;
        As[aCol + 1][aRow] = av.y;
        As[aCol + 2][aRow] = av.z;
        As[aCol + 3][aRow] = av.w;
        // B tile
        if (!TRANS_B) {
            float4 bv = *reinterpret_cast<const float4*>(
                B + (long long)(k0 + bRow) * N + blockIdx.x * BN + bCol);
            *reinterpret_cast<float4*>(&Bs[bRow][bCol]) = bv;
        } else {
            float4 bv = *reinterpret_cast<const float4*>(
                B + (long long)(blockIdx.x * BN + bRow) * K + k0 + bCol);
            Bs[bCol + 0][bRow] = bv.x;
            Bs[bCol + 1][bRow] = bv.y;
            Bs[bCol + 2][bRow] = bv.z;
            Bs[bCol + 3][bRow] = bv.w;
        }
        __syncthreads();

        #pragma unroll
        for (int kk = 0; kk < BK; kk++) {
            float ra[TM], rb[TN];
            #pragma unroll
            for (int i = 0; i < TM; i++) ra[i] = As[kk][ty * TM + i];
            #pragma unroll
            for (int j = 0; j < TN; j++) rb[j] = Bs[kk][tx * TN + j];
            #pragma unroll
            for (int i = 0; i < TM; i++)
                #pragma unroll
                for (int j = 0; j < TN; j++)
                    acc[i][j] += ra[i] * rb[j];
        }
        __syncthreads();
    }

    // epilogue
    #pragma unroll
    for (int i = 0; i < TM; i++) {
        int row = blockIdx.y * BM + ty * TM + i;
        float* crow = Cout + (long long)row * N + blockIdx.x * BN + tx * TN;
        #pragma unroll
        for (int j = 0; j < TN; j++) {
            float v = acc[i][j] * alpha;
            if (HAS_BIAS) v += bias[blockIdx.x * BN + tx * TN + j];
            crow[j] = v;
        }
    }
}

// ---------------- softmax over rows of g_attn (len 2048) --------------------
__global__ void softmax_kernel() {
    __shared__ float shm[9];
    float* row = g_attn + (long long)blockIdx.x * ND;
    int t = threadIdx.x;              // 256 threads, 8 elems each
    float vals[8];
    float m = -INFINITY;
    #pragma unroll
    for (int i = 0; i < 8; i++) {
        vals[i] = row[t + i * 256];
        m = fmaxf(m, vals[i]);
    }
    m = block_max256(m, shm);
    float s = 0.f;
    #pragma unroll
    for (int i = 0; i < 8; i++) {
        vals[i] = expf(vals[i] - m);
        s += vals[i];
    }
    s = block_sum256(s, shm);
    float inv = 1.0f / s;
    #pragma unroll
    for (int i = 0; i < 8; i++) row[t + i * 256] = vals[i] * inv;
}

// ---------------- launch ----------------------------------------------------
extern "C" void kernel_launch(void* const* d_in, const int* in_sizes, int n_in,
                              void* d_out, int out_size) {
    const float* q    = (const float*)d_in[0];
    const float* k    = (const float*)d_in[1];
    const float* v    = (const float*)d_in[2];
    const float* ln_g = (const float*)d_in[3];
    const float* ln_b = (const float*)d_in[4];
    const float* Wq   = (const float*)d_in[5];
    const float* bq   = (const float*)d_in[6];
    const float* Wk   = (const float*)d_in[7];
    const float* bk   = (const float*)d_in[8];
    const float* Wv   = (const float*)d_in[9];
    const float* bv   = (const float*)d_in[10];
    const float* Wo   = (const float*)d_in[11];
    const float* bo   = (const float*)d_in[12];
    float* out = (float*)d_out;

    float *qn, *kn, *vn, *qp, *kp, *vp, *attn, *x;
    cudaGetSymbolAddress((void**)&qn, g_qn);
    cudaGetSymbolAddress((void**)&kn, g_kn);
    cudaGetSymbolAddress((void**)&vn, g_vn);
    cudaGetSymbolAddress((void**)&qp, g_qp);
    cudaGetSymbolAddress((void**)&kp, g_kp);
    cudaGetSymbolAddress((void**)&vp, g_vp);
    cudaGetSymbolAddress((void**)&attn, g_attn);
    cudaGetSymbolAddress((void**)&x, g_x);

    // 1. LayerNorm q,k,v
    ln_kernel<<<dim3(ROWS, 3), 256>>>(q, k, v, ln_g, ln_b);

    // 2. Projections: [8192,256] @ [256,1024] + bias
    {
        dim3 grid(INNER / 128, ROWS / 128, 1);
        gemm_kernel<false, true><<<grid, 256>>>(qn, Wq, bq, qp, ROWS, INNER, CD, 1.0f, 0, 0, 0);
        gemm_kernel<false, true><<<grid, 256>>>(kn, Wk, bk, kp, ROWS, INNER, CD, 1.0f, 0, 0, 0);
        gemm_kernel<false, true><<<grid, 256>>>(vn, Wv, bv, vp, ROWS, INNER, CD, 1.0f, 0, 0, 0);
    }

    // 3. Scores: per batch [2048,1024] @ [2048,1024]^T * SCALE
    {
        dim3 grid(ND / 128, ND / 128, BD);
        gemm_kernel<true, false><<<grid, 256>>>(
            qp, kp, nullptr, attn, ND, ND, INNER, ATT_SCALE,
            (long long)ND * INNER, (long long)ND * INNER, (long long)ND * ND);
    }

    // 4. Softmax rows
    softmax_kernel<<<BD * ND, 256>>>();

    // 5. AV: per batch [2048,2048] @ [2048,1024]
    {
        dim3 grid(INNER / 128, ND / 128, BD);
        gemm_kernel<false, false><<<grid, 256>>>(
            attn, vp, nullptr, x, ND, INNER, ND, 1.0f,
            (long long)ND * ND, (long long)ND * INNER, (long long)ND * INNER);
    }

    // 6. Output projection: [8192,1024] @ [1024,256] + bias
    {
        dim3 grid(CD / 128, ROWS / 128, 1);
        gemm_kernel<false, true><<<grid, 256>>>(x, Wo, bo, out, ROWS, CD, INNER, 1.0f, 0, 0, 0);
    }
}

// round 2
// speedup vs baseline: 3.2155x; 3.2155x over previous
#include <cuda_runtime.h>
#include <math.h>

// Problem constants
#define BD 4
#define ND 2048
#define CD 256
#define INNER 1024
#define ROWS (BD*ND)          // 8192
#define EPS 1e-5f
#define ATT_SCALE 0.125f      // 64^-0.5

// ---------------- scratch (device globals; allocation-free rule) -------------
__device__ float g_qn[ROWS*CD];
__device__ float g_kn[ROWS*CD];
__device__ float g_vn[ROWS*CD];
__device__ float g_qp[ROWS*INNER];
__device__ float g_kp[ROWS*INNER];
__device__ float g_vp[ROWS*INNER];
__device__ float g_attn[(long long)BD*ND*ND];   // 64 MB
__device__ float g_x[ROWS*INNER];

// ---------------- helpers ----------------
__device__ __forceinline__ float warp_sum(float v) {
    #pragma unroll
    for (int o = 16; o; o >>= 1) v += __shfl_xor_sync(0xffffffffu, v, o);
    return v;
}
__device__ __forceinline__ float warp_max(float v) {
    #pragma unroll
    for (int o = 16; o; o >>= 1) v = fmaxf(v, __shfl_xor_sync(0xffffffffu, v, o));
    return v;
}
__device__ __forceinline__ float block_sum256(float v, float* shm) {
    v = warp_sum(v);
    int w = threadIdx.x >> 5;
    if ((threadIdx.x & 31) == 0) shm[w] = v;
    __syncthreads();
    if (threadIdx.x == 0) {
        float s = 0.f;
        #pragma unroll
        for (int i = 0; i < 8; i++) s += shm[i];
        shm[8] = s;
    }
    __syncthreads();
    float r = shm[8];
    __syncthreads();
    return r;
}
__device__ __forceinline__ float block_max256(float v, float* shm) {
    v = warp_max(v);
    int w = threadIdx.x >> 5;
    if ((threadIdx.x & 31) == 0) shm[w] = v;
    __syncthreads();
    if (threadIdx.x == 0) {
        float m = shm[0];
        #pragma unroll
        for (int i = 1; i < 8; i++) m = fmaxf(m, shm[i]);
        shm[8] = m;
    }
    __syncthreads();
    float r = shm[8];
    __syncthreads();
    return r;
}

__device__ __forceinline__ float f2tf(float f) {
    unsigned r;
    asm("cvt.rna.tf32.f32 %0, %1;" : "=r"(r) : "f"(f));
    return __uint_as_float(r);
}

__device__ __forceinline__ void mma_tf32(float* c, const unsigned* a, const unsigned* b) {
    asm volatile(
        "mma.sync.aligned.m16n8k8.row.col.f32.tf32.tf32.f32 "
        "{%0,%1,%2,%3}, {%4,%5,%6,%7}, {%8,%9}, {%0,%1,%2,%3};"
        : "+f"(c[0]), "+f"(c[1]), "+f"(c[2]), "+f"(c[3])
        : "r"(a[0]), "r"(a[1]), "r"(a[2]), "r"(a[3]), "r"(b[0]), "r"(b[1]));
}

// ---------------- LayerNorm ----------------
__global__ void ln_kernel(const float* __restrict__ q, const float* __restrict__ k,
                          const float* __restrict__ v, const float* __restrict__ g,
                          const float* __restrict__ b) {
    __shared__ float shm[9];
    const float* src;
    float* dst;
    int which = blockIdx.y;
    long long off = (long long)blockIdx.x * CD;
    if (which == 0)      { src = q + off; dst = g_qn + off; }
    else if (which == 1) { src = k + off; dst = g_kn + off; }
    else                 { src = v + off; dst = g_vn + off; }

    int t = threadIdx.x;
    float x = src[t];
    float mean = block_sum256(x, shm) * (1.0f / CD);
    float d = x - mean;
    float var = block_sum256(d * d, shm) * (1.0f / CD);
    float inv = rsqrtf(var + EPS);
    dst[t] = d * inv * g[t] + b[t];
}

// ---------------- tf32 tensor-core GEMM ------------------------------------
// C = alpha * A @ B(^T) (+ bias).  A: [M,K] row-major.
// !TRANS_B: B is [K,N] row-major.  TRANS_B: B is [N,K] row-major (use B^T).
// Block tile 128x128x32, 8 warps (4M x 2N), warp tile 32x64, mma m16n8k8.
template<bool TRANS_B, bool HAS_BIAS>
__global__ __launch_bounds__(256)
void mma_gemm(const float* __restrict__ A, const float* __restrict__ B,
              const float* __restrict__ bias, float* __restrict__ Cout,
              int M, int N, int K, float alpha,
              long long strideA, long long strideB, long long strideC) {
    constexpr int BM = 128, BN = 128, BK = 32;
    constexpr int AS = 36;                 // As row stride (floats)
    constexpr int BS_NT = 36;              // Bs[n][k] row stride
    constexpr int BS_NN = 132;             // Bs[k][n] row stride
    constexpr int BSZ = TRANS_B ? BN * BS_NT : BK * BS_NN;

    __shared__ float As[BM * AS];
    __shared__ float Bs[BSZ];

    A    += (long long)blockIdx.z * strideA;
    B    += (long long)blockIdx.z * strideB;
    Cout += (long long)blockIdx.z * strideC;

    const int tid  = threadIdx.x;
    const int lane = tid & 31;
    const int w    = tid >> 5;
    const int g    = lane >> 2;            // group 0..7
    const int tg   = lane & 3;             // thread-in-group 0..3
    const int warpM = (w >> 1) * 32;       // 4 warps in M
    const int warpN = (w & 1) * 64;        // 2 warps in N
    const long long bm = (long long)blockIdx.y * BM;
    const long long bn = (long long)blockIdx.x * BN;

    float acc[2][8][4];
    #pragma unroll
    for (int i = 0; i < 2; i++)
        #pragma unroll
        for (int j = 0; j < 8; j++)
            #pragma unroll
            for (int q_ = 0; q_ < 4; q_++) acc[i][j][q_] = 0.f;

    const int ar = tid >> 3;               // 0..31 (A row within 32-row slab)
    const int ac = (tid & 7) * 4;          // A col (0..28)

    for (int k0 = 0; k0 < K; k0 += BK) {
        // ---- load A tile: 128x32, cvt to tf32 ----
        #pragma unroll
        for (int i = 0; i < 4; i++) {
            int r = ar + i * 32;
            float4 vv = *reinterpret_cast<const float4*>(A + (bm + r) * K + k0 + ac);
            float4 t;
            t.x = f2tf(vv.x); t.y = f2tf(vv.y); t.z = f2tf(vv.z); t.w = f2tf(vv.w);
            *reinterpret_cast<float4*>(&As[r * AS + ac]) = t;
        }
        // ---- load B tile ----
        if (TRANS_B) {
            #pragma unroll
            for (int i = 0; i < 4; i++) {
                int r = ar + i * 32;
                float4 vv = *reinterpret_cast<const float4*>(B + (bn + r) * K + k0 + ac);
                float4 t;
                t.x = f2tf(vv.x); t.y = f2tf(vv.y); t.z = f2tf(vv.z); t.w = f2tf(vv.w);
                *reinterpret_cast<float4*>(&Bs[r * BS_NT + ac]) = t;
            }
        } else {
            #pragma unroll
            for (int i = 0; i < 4; i++) {
                int kk = (tid >> 5) + i * 8;
                int c  = (tid & 31) * 4;
                float4 vv = *reinterpret_cast<const float4*>(B + (long long)(k0 + kk) * N + bn + c);
                float4 t;
                t.x = f2tf(vv.x); t.y = f2tf(vv.y); t.z = f2tf(vv.z); t.w = f2tf(vv.w);
                *reinterpret_cast<float4*>(&Bs[kk * BS_NN + c]) = t;
            }
        }
        __syncthreads();

        // ---- compute: 4 k-steps of 8 ----
        #pragma unroll
        for (int ks = 0; ks < 4; ks++) {
            const int kb = ks * 8;
            unsigned af[2][4];
            #pragma unroll
            for (int mt = 0; mt < 2; mt++) {
                int m = warpM + mt * 16;
                af[mt][0] = __float_as_uint(As[(m + g)     * AS + kb + tg]);
                af[mt][1] = __float_as_uint(As[(m + g + 8) * AS + kb + tg]);
                af[mt][2] = __float_as_uint(As[(m + g)     * AS + kb + tg + 4]);
                af[mt][3] = __float_as_uint(As[(m + g + 8) * AS + kb + tg + 4]);
            }
            unsigned bf[8][2];
            #pragma unroll
            for (int nt = 0; nt < 8; nt++) {
                int n = warpN + nt * 8 + g;
                if (TRANS_B) {
                    bf[nt][0] = __float_as_uint(Bs[n * BS_NT + kb + tg]);
                    bf[nt][1] = __float_as_uint(Bs[n * BS_NT + kb + tg + 4]);
                } else {
                    bf[nt][0] = __float_as_uint(Bs[(kb + tg)     * BS_NN + n]);
                    bf[nt][1] = __float_as_uint(Bs[(kb + tg + 4) * BS_NN + n]);
                }
            }
            #pragma unroll
            for (int mt = 0; mt < 2; mt++)
                #pragma unroll
                for (int nt = 0; nt < 8; nt++)
                    mma_tf32(acc[mt][nt], af[mt], bf[nt]);
        }
        __syncthreads();
    }

    // ---- epilogue ----
    #pragma unroll
    for (int mt = 0; mt < 2; mt++) {
        #pragma unroll
        for (int nt = 0; nt < 8; nt++) {
            long long row0 = bm + warpM + mt * 16 + g;
            long long col  = bn + warpN + nt * 8 + tg * 2;
            float b0 = 0.f, b1 = 0.f;
            if (HAS_BIAS) { b0 = bias[col]; b1 = bias[col + 1]; }
            float2 v0 = make_float2(acc[mt][nt][0] * alpha + b0,
                                    acc[mt][nt][1] * alpha + b1);
            float2 v1 = make_float2(acc[mt][nt][2] * alpha + b0,
                                    acc[mt][nt][3] * alpha + b1);
            *reinterpret_cast<float2*>(Cout + row0 * N + col)       = v0;
            *reinterpret_cast<float2*>(Cout + (row0 + 8) * N + col) = v1;
        }
    }
}

// ---------------- softmax over rows of g_attn (len 2048) --------------------
__global__ void softmax_kernel() {
    __shared__ float shm[9];
    float* row = g_attn + (long long)blockIdx.x * ND;
    int t = threadIdx.x;
    float vals[8];
    float m = -INFINITY;
    #pragma unroll
    for (int i = 0; i < 8; i++) {
        vals[i] = row[t + i * 256];
        m = fmaxf(m, vals[i]);
    }
    m = block_max256(m, shm);
    float s = 0.f;
    #pragma unroll
    for (int i = 0; i < 8; i++) {
        vals[i] = __expf(vals[i] - m);
        s += vals[i];
    }
    s = block_sum256(s, shm);
    float inv = 1.0f / s;
    #pragma unroll
    for (int i = 0; i < 8; i++) row[t + i * 256] = vals[i] * inv;
}

// ---------------- launch ----------------------------------------------------
extern "C" void kernel_launch(void* const* d_in, const int* in_sizes, int n_in,
                              void* d_out, int out_size) {
    const float* q    = (const float*)d_in[0];
    const float* k    = (const float*)d_in[1];
    const float* v    = (const float*)d_in[2];
    const float* ln_g = (const float*)d_in[3];
    const float* ln_b = (const float*)d_in[4];
    const float* Wq   = (const float*)d_in[5];
    const float* bq   = (const float*)d_in[6];
    const float* Wk   = (const float*)d_in[7];
    const float* bk   = (const float*)d_in[8];
    const float* Wv   = (const float*)d_in[9];
    const float* bv   = (const float*)d_in[10];
    const float* Wo   = (const float*)d_in[11];
    const float* bo   = (const float*)d_in[12];
    float* out = (float*)d_out;

    float *qn, *kn, *vn, *qp, *kp, *vp, *attn, *x;
    cudaGetSymbolAddress((void**)&qn, g_qn);
    cudaGetSymbolAddress((void**)&kn, g_kn);
    cudaGetSymbolAddress((void**)&vn, g_vn);
    cudaGetSymbolAddress((void**)&qp, g_qp);
    cudaGetSymbolAddress((void**)&kp, g_kp);
    cudaGetSymbolAddress((void**)&vp, g_vp);
    cudaGetSymbolAddress((void**)&attn, g_attn);
    cudaGetSymbolAddress((void**)&x, g_x);

    // 1. LayerNorm q,k,v
    ln_kernel<<<dim3(ROWS, 3), 256>>>(q, k, v, ln_g, ln_b);

    // 2. Projections: [8192,256] @ [256,1024] + bias
    {
        dim3 grid(INNER / 128, ROWS / 128, 1);
        mma_gemm<false, true><<<grid, 256>>>(qn, Wq, bq, qp, ROWS, INNER, CD, 1.0f, 0, 0, 0);
        mma_gemm<false, true><<<grid, 256>>>(kn, Wk, bk, kp, ROWS, INNER, CD, 1.0f, 0, 0, 0);
        mma_gemm<false, true><<<grid, 256>>>(vn, Wv, bv, vp, ROWS, INNER, CD, 1.0f, 0, 0, 0);
    }

    // 3. Scores: per batch [2048,1024] @ [2048,1024]^T * SCALE
    {
        dim3 grid(ND / 128, ND / 128, BD);
        mma_gemm<true, false><<<grid, 256>>>(
            qp, kp, nullptr, attn, ND, ND, INNER, ATT_SCALE,
            (long long)ND * INNER, (long long)ND * INNER, (long long)ND * ND);
    }

    // 4. Softmax rows
    softmax_kernel<<<BD * ND, 256>>>();

    // 5. AV: per batch [2048,2048] @ [2048,1024]
    {
        dim3 grid(INNER / 128, ND / 128, BD);
        mma_gemm<false, false><<<grid, 256>>>(
            attn, vp, nullptr, x, ND, INNER, ND, 1.0f,
            (long long)ND * ND, (long long)ND * INNER, (long long)ND * INNER);
    }

    // 6. Output projection: [8192,1024] @ [1024,256] + bias
    {
        dim3 grid(CD / 128, ROWS / 128, 1);
        mma_gemm<false, true><<<grid, 256>>>(x, Wo, bo, out, ROWS, CD, INNER, 1.0f, 0, 0, 0);
    }
}